// round 16
// baseline (speedup 1.0000x reference)
#include <cuda_runtime.h>
#include <cuda_bf16.h>
#include <cstdint>

// ---------------- problem constants ----------------
#define MROWS   32768          // B*T
#define NCW     2048
#define DDIM    256
#define NLAYERS 3

// ---------------- tiling (tensor path) ----------------
#define MT      128            // rows per block
#define NT      128            // codewords per N-tile
#define KC      64             // k-chunk (64 bf16 = 128B = SW128 atom row)
#define NCHUNK  (DDIM / KC)    // 4
#define NTILES  (NCW / NT)     // 16
#define TPB     256

#define SPLIT_BYTES (MT * KC * 2)          // one streamed sub-tile: 16384 B
#define STAGE_BYTES (3 * SPLIT_BYTES)      // A-m + B-h + B-m: 49152 B
#define NSTAGE  2
#define DSM_BYTES   (NSTAGE * STAGE_BYTES + 1024)

// rescore margin: tensor-score error (~1e-2 with mm dropped) << DELTA << gap scale
#define RESCORE_DELTA 1.0f

// idesc: kind::f16, dtype F32, a/b BF16, N=128, M=128 (cta_group::1)
#define MMA_IDESC 0x8200490u

// ---------------- tiling (fallback FFMA path) ----------------
#define FB_BK   16
#define FB_LDSROW 132

// Feature gate: tcgen05 only exists in the arch-specific ('a') compilation pass.
#if defined(__CUDA_ARCH__) && (defined(__CUDA_ARCH_FEAT_SM103_ALL) || defined(__CUDA_ARCH_FEAT_SM100_ALL) || defined(__CUDA_ARCH_FEAT_SM101_ALL))
#define HAS_TCGEN05 1
#else
#define HAS_TCGEN05 0
#endif

// ---------------- device scratch (static — no allocation) ----------------
__device__ float g_res[(size_t)MROWS * DDIM];               // fp32 residual
__device__ float g_wsq[NLAYERS * NCW];                      // ||w||^2 exact fp32
__device__ __nv_bfloat16 g_as[2][(size_t)MROWS * DDIM];     // h,m splits of (-2*residual)
__device__ __nv_bfloat16 g_bs[2][(size_t)NLAYERS * NCW * DDIM]; // h,m codebook splits

// ---------------- common helpers ----------------
__device__ __forceinline__ void split2(float x, __nv_bfloat16& h, __nv_bfloat16& m) {
    h = __float2bfloat16(x);
    float r1 = x - __bfloat162float(h);
    m = __float2bfloat16(r1);
}
__device__ __forceinline__ uint32_t pkbf(__nv_bfloat16 a, __nv_bfloat16 b) {
    return (uint32_t)__bfloat16_as_ushort(a) | ((uint32_t)__bfloat16_as_ushort(b) << 16);
}

#if HAS_TCGEN05
// ---------------- PTX helpers (arch-'a' pass only) ----------------
__device__ __forceinline__ uint32_t smem_u32(const void* p) {
    uint32_t a;
    asm("{ .reg .u64 t; cvta.to.shared.u64 t, %1; cvt.u32.u64 %0, t; }"
        : "=r"(a) : "l"(p));
    return a;
}
#define TC_ALLOC(smemaddr, n) \
    asm volatile("tcgen05.alloc.cta_group::1.sync.aligned.shared::cta.b32 [%0], %1;" \
                 :: "r"(smemaddr), "r"((uint32_t)(n)) : "memory")
#define TC_RELINQ() \
    asm volatile("tcgen05.relinquish_alloc_permit.cta_group::1.sync.aligned;")
#define TC_DEALLOC(tmem, n) \
    asm volatile("tcgen05.dealloc.cta_group::1.sync.aligned.b32 %0, %1;" \
                 :: "r"(tmem), "r"((uint32_t)(n)))
#define TC_COMMIT(mbar) \
    asm volatile("tcgen05.commit.cta_group::1.mbarrier::arrive::one.shared::cluster.b64 [%0];" \
                 :: "r"(mbar) : "memory")
#define TC_WAIT_LD()  asm volatile("tcgen05.wait::ld.sync.aligned;" ::: "memory")
#define TC_WAIT_ST()  asm volatile("tcgen05.wait::st.sync.aligned;" ::: "memory")
#define TC_FENCE_AFTER()  asm volatile("tcgen05.fence::after_thread_sync;" ::: "memory")
#define TC_FENCE_BEFORE() asm volatile("tcgen05.fence::before_thread_sync;" ::: "memory")
#define FENCE_PROXY() asm volatile("fence.proxy.async.shared::cta;" ::: "memory")
#define CP_ASYNC16(smem_addr, gptr) \
    asm volatile("cp.async.cg.shared.global [%0], [%1], 16;" \
                 :: "r"(smem_addr), "l"(gptr) : "memory")
#define CP_ASYNC_WAIT_ALL() \
    asm volatile("cp.async.commit_group;\n\tcp.async.wait_group 0;" ::: "memory")
#define MBAR_INIT(mbar, cnt) \
    asm volatile("mbarrier.init.shared.b64 [%0], %1;" :: "r"(mbar), "r"((uint32_t)(cnt)) : "memory")
#define MBAR_INVAL(mbar) \
    asm volatile("mbarrier.inval.shared.b64 [%0];" :: "r"(mbar) : "memory")
#define MBAR_ARRIVE(mbar) \
    asm volatile("mbarrier.arrive.shared.b64 _, [%0];" :: "r"(mbar) : "memory")
#define MBAR_WAIT(mbar, parity) do {                                            \
    uint32_t _m = (mbar); uint32_t _p = (parity); uint32_t _d;                  \
    asm volatile("{\n\t.reg .pred p;\n\t"                                       \
        "mbarrier.try_wait.parity.acquire.cta.shared::cta.b64 p, [%1], %2;\n\t" \
        "selp.b32 %0, 1, 0, p;\n\t}" : "=r"(_d) : "r"(_m), "r"(_p) : "memory"); \
    if (!_d) {                                                                  \
        asm volatile("{\n\t.reg .pred P1;\n\t"                                  \
            "WL_%=:\n\t"                                                        \
            "mbarrier.try_wait.parity.acquire.cta.shared::cta.b64 P1, [%0], %1, 0x989680;\n\t" \
            "@P1 bra.uni WD_%=;\n\t"                                            \
            "bra.uni WL_%=;\n\t"                                                \
            "WD_%=:\n\t}" :: "r"(_m), "r"(_p) : "memory");                      \
    }                                                                           \
} while (0)

// TS-mode MMA: A in TMEM, B via smem descriptor.
__device__ __forceinline__ void mma_f16_ts(uint32_t d, uint32_t a_tmem, uint64_t bd,
                                           uint32_t idesc, bool accum) {
    uint32_t e = accum ? 1u : 0u, z = 0u;
    asm volatile("{\n\t.reg .pred p;\n\tsetp.ne.u32 p, %5, 0;\n\t"
                 "tcgen05.mma.cta_group::1.kind::f16 [%0], [%1], %2, %3, {%4,%4,%4,%4}, p;\n\t}"
                 :: "r"(d), "r"(a_tmem), "l"(bd), "r"(idesc), "r"(z), "r"(e) : "memory");
}
// SS-mode MMA: A and B via smem descriptors.
__device__ __forceinline__ void mma_f16_ss(uint32_t d, uint64_t ad, uint64_t bd,
                                           uint32_t idesc, bool accum) {
    uint32_t e = accum ? 1u : 0u, z = 0u;
    asm volatile("{\n\t.reg .pred p;\n\tsetp.ne.u32 p, %5, 0;\n\t"
                 "tcgen05.mma.cta_group::1.kind::f16 [%0], %1, %2, %3, {%4,%4,%4,%4}, p;\n\t}"
                 :: "r"(d), "l"(ad), "l"(bd), "r"(idesc), "r"(z), "r"(e) : "memory");
}
__device__ __forceinline__ void ldtm_x32(uint32_t* r, uint32_t addr) {
    asm volatile("tcgen05.ld.sync.aligned.32x32b.x32.b32 "
        "{%0,%1,%2,%3,%4,%5,%6,%7,%8,%9,%10,%11,%12,%13,%14,%15,"
        "%16,%17,%18,%19,%20,%21,%22,%23,%24,%25,%26,%27,%28,%29,%30,%31}, [%32];"
        : "=r"(r[0]),"=r"(r[1]),"=r"(r[2]),"=r"(r[3]),"=r"(r[4]),"=r"(r[5]),"=r"(r[6]),"=r"(r[7]),
          "=r"(r[8]),"=r"(r[9]),"=r"(r[10]),"=r"(r[11]),"=r"(r[12]),"=r"(r[13]),"=r"(r[14]),"=r"(r[15]),
          "=r"(r[16]),"=r"(r[17]),"=r"(r[18]),"=r"(r[19]),"=r"(r[20]),"=r"(r[21]),"=r"(r[22]),"=r"(r[23]),
          "=r"(r[24]),"=r"(r[25]),"=r"(r[26]),"=r"(r[27]),"=r"(r[28]),"=r"(r[29]),"=r"(r[30]),"=r"(r[31])
        : "r"(addr));
}
__device__ __forceinline__ void sttm_x32(uint32_t addr, const uint32_t* r) {
    asm volatile("tcgen05.st.sync.aligned.32x32b.x32.b32 [%0], "
        "{%1,%2,%3,%4,%5,%6,%7,%8,%9,%10,%11,%12,%13,%14,%15,%16,"
        "%17,%18,%19,%20,%21,%22,%23,%24,%25,%26,%27,%28,%29,%30,%31,%32};"
        :: "r"(addr),
           "r"(r[0]),"r"(r[1]),"r"(r[2]),"r"(r[3]),"r"(r[4]),"r"(r[5]),"r"(r[6]),"r"(r[7]),
           "r"(r[8]),"r"(r[9]),"r"(r[10]),"r"(r[11]),"r"(r[12]),"r"(r[13]),"r"(r[14]),"r"(r[15]),
           "r"(r[16]),"r"(r[17]),"r"(r[18]),"r"(r[19]),"r"(r[20]),"r"(r[21]),"r"(r[22]),"r"(r[23]),
           "r"(r[24]),"r"(r[25]),"r"(r[26]),"r"(r[27]),"r"(r[28]),"r"(r[29]),"r"(r[30]),"r"(r[31])
        : "memory");
}
__device__ __forceinline__ uint64_t make_desc(uint32_t addr) {
    const uint64_t base = (2ull << 61) | (1ull << 46) | (64ull << 32) | (1ull << 16);
    return base | ((uint64_t)(addr >> 4) & 0x3FFF);
}
#define SWZ(o) ((o) ^ (((o) >> 3) & 0x70))

// One 32-element argmin chain update (independent per group).
__device__ __forceinline__ void scan32(const uint32_t* d, const float* wq, int colbase,
                                       float& bS, int& bI, float& sS, int& sI) {
#pragma unroll
    for (int j = 0; j < 32; j++) {
        float s = wq[j] + __uint_as_float(d[j]);
        if (s < bS) { sS = bS; sI = bI; bS = s; bI = colbase + j; }
        else if (s < sS) { sS = s; sI = colbase + j; }
    }
}
#endif  // HAS_TCGEN05

// ---------------- fused prep kernel: hsplit + cbsplit + wsq in one launch ----------------
#define HS_TOT (MROWS * DDIM / 4)                 // 2,097,152 float4 items
#define CS_TOT (NLAYERS * NCW * DDIM / 4)         // 393,216 float4 items
#define WQ_TOT (NLAYERS * NCW)                    // 6,144 row items
#define PREP_TOT (HS_TOT + CS_TOT + WQ_TOT)

__global__ void prep_kernel(const float* __restrict__ hin, const float* __restrict__ cb) {
    size_t f = (size_t)blockIdx.x * 256 + threadIdx.x;
    if (f < HS_TOT) {
        float4 v = reinterpret_cast<const float4*>(hin)[f];
        float e[4] = {-2.f * v.x, -2.f * v.y, -2.f * v.z, -2.f * v.w};
        __nv_bfloat16 h[4], m[4];
#pragma unroll
        for (int k = 0; k < 4; k++) split2(e[k], h[k], m[k]);
        reinterpret_cast<uint2*>(g_as[0])[f] = make_uint2(pkbf(h[0], h[1]), pkbf(h[2], h[3]));
        reinterpret_cast<uint2*>(g_as[1])[f] = make_uint2(pkbf(m[0], m[1]), pkbf(m[2], m[3]));
    } else if (f < HS_TOT + CS_TOT) {
        size_t i4 = f - HS_TOT;
        float4 v = reinterpret_cast<const float4*>(cb)[i4];
        float e[4] = {v.x, v.y, v.z, v.w};
        __nv_bfloat16 h[4], m[4];
#pragma unroll
        for (int k = 0; k < 4; k++) split2(e[k], h[k], m[k]);
        reinterpret_cast<uint2*>(g_bs[0])[i4] = make_uint2(pkbf(h[0], h[1]), pkbf(h[2], h[3]));
        reinterpret_cast<uint2*>(g_bs[1])[i4] = make_uint2(pkbf(m[0], m[1]), pkbf(m[2], m[3]));
    } else if (f < PREP_TOT) {
        int r = (int)(f - HS_TOT - CS_TOT);
        const float4* p = reinterpret_cast<const float4*>(cb + (size_t)r * DDIM);
        float s = 0.f;
#pragma unroll
        for (int i = 0; i < DDIM / 4; i++) {
            float4 v = p[i];
            s += v.x * v.x + v.y * v.y + v.z * v.z + v.w * v.w;
        }
        g_wsq[r] = s;
    }
}

// ---------------- main fused layer kernel ----------------
template <int LAYER>
__global__ void __launch_bounds__(TPB, 2)
rvq_tc_kernel(const float* __restrict__ hin,
              const float* __restrict__ codebooks,
              float* __restrict__ qout,
              float* __restrict__ idxout)
{
#if HAS_TCGEN05
    extern __shared__ char dsm_raw[];
    __shared__ float swsq[NCW];
    __shared__ int sIdx[MT];
    __shared__ uint32_t sTmem[1];
    __shared__ __align__(8) unsigned long long sBar[6];
    // sBar: 0,1 = full[stage]; 2,3 = done[stage]; 4 = tile-done; 5 = readers-done

    const int tid = threadIdx.x;
    const int wid = tid >> 5;
    const int row0 = blockIdx.x * MT;

    uint32_t dynb = (smem_u32(dsm_raw) + 1023u) & ~1023u;   // 1024-aligned stage base
    const uint32_t mbFull0 = smem_u32(&sBar[0]);
    const uint32_t mbFull1 = smem_u32(&sBar[1]);
    const uint32_t mbDone0 = smem_u32(&sBar[2]);
    const uint32_t mbDone1 = smem_u32(&sBar[3]);
    const uint32_t mbNT    = smem_u32(&sBar[4]);
    const uint32_t mbRead  = smem_u32(&sBar[5]);
    const uint32_t tptr = smem_u32(&sTmem[0]);

    const float* rin = (LAYER == 0) ? hin : g_res;
    const float* cb  = codebooks + (size_t)LAYER * NCW * DDIM;

    const __nv_bfloat16* ah = g_as[0] + (size_t)row0 * DDIM;   // A h-split (TMEM-bound)
    const __nv_bfloat16* am = g_as[1] + (size_t)row0 * DDIM;   // A m-split (streamed)
    const __nv_bfloat16* bh = g_bs[0] + (size_t)LAYER * NCW * DDIM;
    const __nv_bfloat16* bm = g_bs[1] + (size_t)LAYER * NCW * DDIM;

    if (wid == 0) {
        TC_ALLOC(tptr, 256);   // D: cols 0..127, A-h (full K): cols 128..255
        TC_RELINQ();
    }
    if (tid == 0) {
        MBAR_INIT(mbFull0, 128);
        MBAR_INIT(mbFull1, 128);
        MBAR_INIT(mbDone0, 1);
        MBAR_INIT(mbDone1, 1);
        MBAR_INIT(mbNT, 1);
        MBAR_INIT(mbRead, 128);
    }
    for (int i = tid; i < NCW; i += TPB) swsq[i] = g_wsq[LAYER * NCW + i];
    __syncthreads();
    const uint32_t tmem = sTmem[0];

    if (tid < 128) {
        // ---- consumers (warps 0-3) + MMA issuer (tid 0) ----
        const uint32_t woff = ((uint32_t)tid >> 5) << 21;

        // Load A-h split (row = tid, 256 bf16 = 128 TMEM cols) into TMEM.
        {
            const uint4* src = reinterpret_cast<const uint4*>(ah + (size_t)tid * DDIM);
#pragma unroll
            for (int g = 0; g < 4; g++) {
                uint32_t u[32];
#pragma unroll
                for (int q = 0; q < 8; q++) {
                    uint4 v = src[g * 8 + q];
                    u[q * 4 + 0] = v.x; u[q * 4 + 1] = v.y;
                    u[q * 4 + 2] = v.z; u[q * 4 + 3] = v.w;
                }
                sttm_x32(tmem + 128 + g * 32 + woff, u);
            }
        }
        TC_WAIT_ST();
        TC_FENCE_BEFORE();
        asm volatile("bar.sync 1, 128;" ::: "memory");   // all A-h rows in TMEM

        // 4 independent argmin chains (one per 32-col group), merged after the loop.
        float bS[4], sS[4];
        int   bI[4], sI[4];
#pragma unroll
        for (int g = 0; g < 4; g++) { bS[g] = 3.4e38f; sS[g] = 3.4e38f; bI[g] = 0; sI[g] = 0; }

#pragma unroll 1
        for (int nt = 0; nt < NTILES; nt++) {
            if (tid == 0) {
                if (nt > 0) MBAR_WAIT(mbRead, (nt - 1) & 1);  // D readers done
#pragma unroll 1
                for (int kc = 0; kc < NCHUNK; kc++) {
                    int itc = nt * NCHUNK + kc;
                    int st  = itc & 1;
                    int u   = itc >> 1;
                    MBAR_WAIT(st ? mbFull1 : mbFull0, u & 1);
                    uint64_t am_d = make_desc(dynb + st * STAGE_BYTES + 0 * SPLIT_BYTES);
                    uint64_t bh_d = make_desc(dynb + st * STAGE_BYTES + 1 * SPLIT_BYTES);
                    uint64_t bm_d = make_desc(dynb + st * STAGE_BYTES + 2 * SPLIT_BYTES);
                    uint32_t ah_t = tmem + 128 + kc * 32;
#pragma unroll
                    for (int ks = 0; ks < 4; ks++) {
                        bool first = (kc == 0 && ks == 0);
                        mma_f16_ts(tmem, ah_t + ks * 8, bh_d + ks * 2, MMA_IDESC, !first);  // hh
                        mma_f16_ts(tmem, ah_t + ks * 8, bm_d + ks * 2, MMA_IDESC, true);    // hm
                        mma_f16_ss(tmem, am_d + ks * 2, bh_d + ks * 2, MMA_IDESC, true);    // mh
                    }
                    TC_COMMIT(st ? mbDone1 : mbDone0);
                    if (kc == NCHUNK - 1) TC_COMMIT(mbNT);
                }
            }
            MBAR_WAIT(mbNT, nt & 1);   // all of this tile's MMAs complete
            TC_FENCE_AFTER();

            float wq[32];
            // Pair 1: groups 0,1 — load, then scan (blocking window).
            uint32_t d0[32], d1[32];
            ldtm_x32(d0, tmem + 0);
            ldtm_x32(d1, tmem + 32);
            TC_WAIT_LD();
#pragma unroll
            for (int j = 0; j < 32; j++) wq[j] = swsq[nt * NT + j];
            scan32(d0, wq, nt * NT, bS[0], bI[0], sS[0], sI[0]);
#pragma unroll
            for (int j = 0; j < 32; j++) wq[j] = swsq[nt * NT + 32 + j];
            scan32(d1, wq, nt * NT + 32, bS[1], bI[1], sS[1], sI[1]);
            // Pair 2: groups 2,3 — load, release D, then scan off the blocking path.
            ldtm_x32(d0, tmem + 64);
            ldtm_x32(d1, tmem + 96);
            TC_WAIT_LD();
            TC_FENCE_BEFORE();
            MBAR_ARRIVE(mbRead);       // D free: next tile's MMAs may start
#pragma unroll
            for (int j = 0; j < 32; j++) wq[j] = swsq[nt * NT + 64 + j];
            scan32(d0, wq, nt * NT + 64, bS[2], bI[2], sS[2], sI[2]);
#pragma unroll
            for (int j = 0; j < 32; j++) wq[j] = swsq[nt * NT + 96 + j];
            scan32(d1, wq, nt * NT + 96, bS[3], bI[3], sS[3], sI[3]);
        }

        // Merge the 4 chains' top-2 into a global top-2 (lower index wins ties).
        float cS[8];
        int   cI[8];
#pragma unroll
        for (int g = 0; g < 4; g++) {
            cS[g * 2] = bS[g];     cI[g * 2] = bI[g];
            cS[g * 2 + 1] = sS[g]; cI[g * 2 + 1] = sI[g];
        }
        float bestS = 3.4e38f, secS = 3.4e38f;
        int   bestI = 0,       secI = 0;
#pragma unroll
        for (int k = 0; k < 8; k++) {
            float s = cS[k]; int i = cI[k];
            if (s < bestS || (s == bestS && i < bestI)) {
                if (bestS < s || (bestS == s && bestI < i)) { /* unreachable */ }
                secS = bestS; secI = bestI;
                bestS = s; bestI = i;
            } else if (s < secS || (s == secS && i < secI)) {
                secS = s; secI = i;
            }
        }

        // Exact fp32 rescore when contested (round-3-proven decision procedure).
        int win = bestI;
        if (secS - bestS < RESCORE_DELTA) {
            int c1 = bestI, c2 = secI;
            const float4* rp  = reinterpret_cast<const float4*>(rin + (size_t)(row0 + tid) * DDIM);
            const float4* w1p = reinterpret_cast<const float4*>(cb + (size_t)c1 * DDIM);
            const float4* w2p = reinterpret_cast<const float4*>(cb + (size_t)c2 * DDIM);
            float a1 = 0.f, a2 = 0.f;
#pragma unroll 8
            for (int i = 0; i < DDIM / 4; i++) {
                float4 rv = rp[i];
                float4 w1 = w1p[i];
                float4 w2 = w2p[i];
                a1 = fmaf(rv.x, w1.x, a1); a1 = fmaf(rv.y, w1.y, a1);
                a1 = fmaf(rv.z, w1.z, a1); a1 = fmaf(rv.w, w1.w, a1);
                a2 = fmaf(rv.x, w2.x, a2); a2 = fmaf(rv.y, w2.y, a2);
                a2 = fmaf(rv.z, w2.z, a2); a2 = fmaf(rv.w, w2.w, a2);
            }
            float s1 = fmaf(-2.f, a1, swsq[c1]);
            float s2 = fmaf(-2.f, a2, swsq[c2]);
            win = (s2 < s1 || (s2 == s1 && c2 < c1)) ? c2 : c1;
        }
        sIdx[tid] = win;
        if (idxout) idxout[LAYER * MROWS + row0 + tid] = (float)win;
    } else {
        // ---- producers (warps 4-7): A-m + B-h + B-m chunks via cp.async, 2-stage ----
        const int ptid = tid - 128;
#pragma unroll 1
        for (int itc = 0; itc < NTILES * NCHUNK; itc++) {
            int st = itc & 1;
            int u  = itc >> 1;
            if (u > 0) MBAR_WAIT(st ? mbDone1 : mbDone0, (u - 1) & 1);
            int nt = itc >> 2;
            int kc = itc & 3;
#pragma unroll
            for (int i = 0; i < 24; i++) {
                int f   = i * 128 + ptid;     // 0..3071
                int s   = f >> 10;            // sub-tile: 0=A-m, 1=B-h, 2=B-m
                int rem = f & 1023;
                int r   = rem >> 3;           // row 0..127
                int j   = rem & 7;            // 16B group within 128B row
                const __nv_bfloat16* src;
                if (s == 0)      src = am + (size_t)r * DDIM + kc * KC + j * 8;
                else if (s == 1) src = bh + (size_t)(nt * NT + r) * DDIM + kc * KC + j * 8;
                else             src = bm + (size_t)(nt * NT + r) * DDIM + kc * KC + j * 8;
                uint32_t dst = dynb + st * STAGE_BYTES + s * SPLIT_BYTES + SWZ(r * 128 + j * 16);
                CP_ASYNC16(dst, src);
            }
            CP_ASYNC_WAIT_ALL();
            FENCE_PROXY();
            MBAR_ARRIVE(st ? mbFull1 : mbFull0);
        }
    }
    __syncthreads();

    // fused epilogue: gather winner, quant accumulate, residual + next-layer splits
#pragma unroll 4
    for (int it = 0; it < 32; it++) {
        int f   = it * TPB + tid;   // 0..8191
        int rr  = f >> 6;           // row 0..127
        int c4  = f & 63;           // float4 over D
        int row = row0 + rr;
        int w   = sIdx[rr];
        float4 wv = *reinterpret_cast<const float4*>(cb + (size_t)w * DDIM + c4 * 4);
        float4* qp = reinterpret_cast<float4*>(qout + (size_t)row * DDIM + c4 * 4);
        if (LAYER == 0) {
            *qp = wv;
        } else {
            float4 q = *qp;
            q.x += wv.x; q.y += wv.y; q.z += wv.z; q.w += wv.w;
            *qp = q;
        }
        if (LAYER < 2) {
            float4 rv = *reinterpret_cast<const float4*>(rin + (size_t)row * DDIM + c4 * 4);
            float4 nr = make_float4(rv.x - wv.x, rv.y - wv.y, rv.z - wv.z, rv.w - wv.w);
            *reinterpret_cast<float4*>(g_res + (size_t)row * DDIM + c4 * 4) = nr;
            float e[4] = {-2.f * nr.x, -2.f * nr.y, -2.f * nr.z, -2.f * nr.w};
            __nv_bfloat16 h[4], m[4];
#pragma unroll
            for (int k = 0; k < 4; k++) split2(e[k], h[k], m[k]);
            size_t o2 = ((size_t)row * DDIM + c4 * 4) / 4;   // uint2 index
            reinterpret_cast<uint2*>(g_as[0])[o2] = make_uint2(pkbf(h[0], h[1]), pkbf(h[2], h[3]));
            reinterpret_cast<uint2*>(g_as[1])[o2] = make_uint2(pkbf(m[0], m[1]), pkbf(m[2], m[3]));
        }
    }

    __syncthreads();
    if (tid == 0) {
        MBAR_INVAL(mbFull0); MBAR_INVAL(mbFull1);
        MBAR_INVAL(mbDone0); MBAR_INVAL(mbDone1);
        MBAR_INVAL(mbNT);    MBAR_INVAL(mbRead);
    }
    __syncthreads();
    if (wid == 0) TC_DEALLOC(tmem, 256);

#else  // ---------------- fallback: exact-fp32 FFMA path (round-3 body) ----------------

    __shared__ unsigned int smemU[4480];
    float* As = reinterpret_cast<float*>(smemU);                 // [FB_BK][FB_LDSROW]
    float* Bs = As + FB_BK * FB_LDSROW;                          // [FB_BK][FB_LDSROW]
    float* redS = reinterpret_cast<float*>(smemU);               // [128][17]
    int*   redI = reinterpret_cast<int*>(smemU + 128 * 17);      // [128][17]
    __shared__ int sIdx[MT];

    const float* rin = (LAYER == 0) ? hin : g_res;
    const float* cb  = codebooks + (size_t)LAYER * NCW * DDIM;
    const float* wsq = g_wsq + LAYER * NCW;

    const int tid   = threadIdx.x;
    const int wid   = tid >> 5;
    const int lane  = tid & 31;
    const int warpR = wid >> 1;
    const int warpC = wid & 1;
    const int r     = lane >> 3;
    const int c     = lane & 7;

    const int rowA0 = warpR * 32 + r * 4;
    const int rowA1 = rowA0 + 16;
    const int colB0 = warpC * 64 + c * 4;
    const int colB1 = colB0 + 32;

    const int row0 = blockIdx.x * MT;
    const int ldrow = tid >> 2;
    const int ldkq  = tid & 3;

    float bestS[8];
    int   bestI[8];
#pragma unroll
    for (int j = 0; j < 8; j++) { bestS[j] = 1e30f; bestI[j] = 0; }

    const float* aG = rin + (size_t)row0 * DDIM;

#pragma unroll 1
    for (int nt = 0; nt < NCW / NT; nt++) {
        float acc[8][8];
#pragma unroll
        for (int j = 0; j < 8; j++)
#pragma unroll
            for (int p = 0; p < 8; p++) acc[j][p] = 0.f;

        const float* bG = cb + (size_t)(nt * NT) * DDIM;

#pragma unroll 1
        for (int kc = 0; kc < DDIM / FB_BK; kc++) {
            __syncthreads();
#pragma unroll
            for (int i = 0; i < 2; i++) {
                int row = i * 64 + ldrow;
                float4 av = *reinterpret_cast<const float4*>(
                    aG + (size_t)row * DDIM + kc * FB_BK + ldkq * 4);
                float4 bv = *reinterpret_cast<const float4*>(
                    bG + (size_t)row * DDIM + kc * FB_BK + ldkq * 4);
                As[(ldkq * 4 + 0) * FB_LDSROW + row] = av.x;
                As[(ldkq * 4 + 1) * FB_LDSROW + row] = av.y;
                As[(ldkq * 4 + 2) * FB_LDSROW + row] = av.z;
                As[(ldkq * 4 + 3) * FB_LDSROW + row] = av.w;
                Bs[(ldkq * 4 + 0) * FB_LDSROW + row] = bv.x;
                Bs[(ldkq * 4 + 1) * FB_LDSROW + row] = bv.y;
                Bs[(ldkq * 4 + 2) * FB_LDSROW + row] = bv.z;
                Bs[(ldkq * 4 + 3) * FB_LDSROW + row] = bv.w;
            }
            __syncthreads();

#pragma unroll
            for (int k = 0; k < FB_BK; k++) {
                const float* ak = As + k * FB_LDSROW;
                const float* bk = Bs + k * FB_LDSROW;
                float4 a0 = *reinterpret_cast<const float4*>(ak + rowA0);
                float4 a1 = *reinterpret_cast<const float4*>(ak + rowA1);
                float4 b0 = *reinterpret_cast<const float4*>(bk + colB0);
                float4 b1 = *reinterpret_cast<const float4*>(bk + colB1);
                float af[8] = {a0.x, a0.y, a0.z, a0.w, a1.x, a1.y, a1.z, a1.w};
                float bf[8] = {b0.x, b0.y, b0.z, b0.w, b1.x, b1.y, b1.z, b1.w};
#pragma unroll
                for (int j = 0; j < 8; j++)
#pragma unroll
                    for (int p = 0; p < 8; p++)
                        acc[j][p] = fmaf(af[j], bf[p], acc[j][p]);
            }
        }

        float4 w0 = *reinterpret_cast<const float4*>(wsq + nt * NT + colB0);
        float4 w1 = *reinterpret_cast<const float4*>(wsq + nt * NT + colB1);
        float wv[8] = {w0.x, w0.y, w0.z, w0.w, w1.x, w1.y, w1.z, w1.w};
#pragma unroll
        for (int j = 0; j < 8; j++) {
#pragma unroll
            for (int p = 0; p < 8; p++) {
                int col = nt * NT + ((p < 4) ? (colB0 + p) : (colB1 + p - 4));
                float s = fmaf(-2.f, acc[j][p], wv[p]);
                if (s < bestS[j]) { bestS[j] = s; bestI[j] = col; }
            }
        }
    }

    __syncthreads();
    {
        int slot = warpC * 8 + c;
#pragma unroll
        for (int j = 0; j < 8; j++) {
            int rl = warpR * 32 + ((j < 4) ? 0 : 16) + r * 4 + (j & 3);
            redS[rl * 17 + slot] = bestS[j];
            redI[rl * 17 + slot] = bestI[j];
        }
    }
    __syncthreads();
    if (tid < MT) {
        float bs = redS[tid * 17];
        int   bi = redI[tid * 17];
#pragma unroll
        for (int x = 1; x < 16; x++) {
            float s  = redS[tid * 17 + x];
            int   ii = redI[tid * 17 + x];
            if (s < bs || (s == bs && ii < bi)) { bs = s; bi = ii; }
        }
        sIdx[tid] = bi;
        if (idxout) idxout[LAYER * MROWS + row0 + tid] = (float)bi;
    }
    __syncthreads();

#pragma unroll 4
    for (int it = 0; it < 32; it++) {
        int f   = it * TPB + tid;
        int rr  = f >> 6;
        int c4  = f & 63;
        int row = row0 + rr;
        int w   = sIdx[rr];
        float4 wv = *reinterpret_cast<const float4*>(cb + (size_t)w * DDIM + c4 * 4);
        float4 rv = *reinterpret_cast<const float4*>(rin + (size_t)row * DDIM + c4 * 4);
        float4 nr = make_float4(rv.x - wv.x, rv.y - wv.y, rv.z - wv.z, rv.w - wv.w);
        *reinterpret_cast<float4*>(g_res + (size_t)row * DDIM + c4 * 4) = nr;
        float4* qp = reinterpret_cast<float4*>(qout + (size_t)row * DDIM + c4 * 4);
        if (LAYER == 0) {
            *qp = wv;
        } else {
            float4 q = *qp;
            q.x += wv.x; q.y += wv.y; q.z += wv.z; q.w += wv.w;
            *qp = q;
        }
    }
#endif  // HAS_TCGEN05
}

// ---------------- host launcher ----------------
extern "C" void kernel_launch(void* const* d_in, const int* in_sizes, int n_in,
                              void* d_out, int out_size) {
    (void)in_sizes; (void)n_in;
    const float* h  = (const float*)d_in[0];
    const float* cb = (const float*)d_in[1];
    float* out = (float*)d_out;

    const long long QN = (long long)MROWS * DDIM;     // 8,388,608
    const long long IN = (long long)NLAYERS * MROWS;  // 98,304
    float* qout   = out;
    float* idxout = ((long long)out_size >= QN + IN) ? out + QN : nullptr;

    cudaFuncSetAttribute(rvq_tc_kernel<0>, cudaFuncAttributeMaxDynamicSharedMemorySize, DSM_BYTES);
    cudaFuncSetAttribute(rvq_tc_kernel<1>, cudaFuncAttributeMaxDynamicSharedMemorySize, DSM_BYTES);
    cudaFuncSetAttribute(rvq_tc_kernel<2>, cudaFuncAttributeMaxDynamicSharedMemorySize, DSM_BYTES);

    prep_kernel<<<(PREP_TOT + 255) / 256, 256>>>(h, cb);

    rvq_tc_kernel<0><<<MROWS / MT, TPB, DSM_BYTES>>>(h, cb, qout, idxout);
    rvq_tc_kernel<1><<<MROWS / MT, TPB, DSM_BYTES>>>(h, cb, qout, idxout);
    rvq_tc_kernel<2><<<MROWS / MT, TPB, DSM_BYTES>>>(h, cb, qout, idxout);
}

// round 17
// speedup vs baseline: 1.8744x; 1.8744x over previous
#include <cuda_runtime.h>
#include <cuda_bf16.h>
#include <cstdint>

// ---------------- problem constants ----------------
#define MROWS   32768          // B*T
#define NCW     2048
#define DDIM    256
#define NLAYERS 3

// ---------------- tiling (tensor path) ----------------
#define MT      128            // rows per block
#define NT      128            // codewords per N-tile
#define KC      64             // k-chunk (64 bf16 = 128B = SW128 atom row)
#define NCHUNK  (DDIM / KC)    // 4
#define NTILES  (NCW / NT)     // 16
#define TPB     256

#define SPLIT_BYTES (MT * KC * 2)          // one streamed sub-tile: 16384 B
#define STAGE_BYTES (3 * SPLIT_BYTES)      // A-m + B-h + B-m: 49152 B
#define NSTAGE  2
#define DSM_BYTES   (NSTAGE * STAGE_BYTES + 1024)

// rescore margin: tensor-score error (~1e-2 with mm dropped) << DELTA << gap scale
#define RESCORE_DELTA 1.0f

// idesc: kind::f16, dtype F32, a/b BF16, N=128, M=128 (cta_group::1)
#define MMA_IDESC 0x8200490u

// ---------------- tiling (fallback FFMA path) ----------------
#define FB_BK   16
#define FB_LDSROW 132

// Feature gate: tcgen05 only exists in the arch-specific ('a') compilation pass.
#if defined(__CUDA_ARCH__) && (defined(__CUDA_ARCH_FEAT_SM103_ALL) || defined(__CUDA_ARCH_FEAT_SM100_ALL) || defined(__CUDA_ARCH_FEAT_SM101_ALL))
#define HAS_TCGEN05 1
#else
#define HAS_TCGEN05 0
#endif

// ---------------- device scratch (static — no allocation) ----------------
__device__ float g_res[(size_t)MROWS * DDIM];               // fp32 residual
__device__ float g_wsq[NLAYERS * NCW];                      // ||w||^2 exact fp32
__device__ __nv_bfloat16 g_as[2][(size_t)MROWS * DDIM];     // h,m splits of (-2*residual)
__device__ __nv_bfloat16 g_bs[2][(size_t)NLAYERS * NCW * DDIM]; // h,m codebook splits

// ---------------- common helpers ----------------
__device__ __forceinline__ void split2(float x, __nv_bfloat16& h, __nv_bfloat16& m) {
    h = __float2bfloat16(x);
    float r1 = x - __bfloat162float(h);
    m = __float2bfloat16(r1);
}
__device__ __forceinline__ uint32_t pkbf(__nv_bfloat16 a, __nv_bfloat16 b) {
    return (uint32_t)__bfloat16_as_ushort(a) | ((uint32_t)__bfloat16_as_ushort(b) << 16);
}

#if HAS_TCGEN05
// ---------------- PTX helpers (arch-'a' pass only) ----------------
__device__ __forceinline__ uint32_t smem_u32(const void* p) {
    uint32_t a;
    asm("{ .reg .u64 t; cvta.to.shared.u64 t, %1; cvt.u32.u64 %0, t; }"
        : "=r"(a) : "l"(p));
    return a;
}
#define TC_ALLOC(smemaddr, n) \
    asm volatile("tcgen05.alloc.cta_group::1.sync.aligned.shared::cta.b32 [%0], %1;" \
                 :: "r"(smemaddr), "r"((uint32_t)(n)) : "memory")
#define TC_RELINQ() \
    asm volatile("tcgen05.relinquish_alloc_permit.cta_group::1.sync.aligned;")
#define TC_DEALLOC(tmem, n) \
    asm volatile("tcgen05.dealloc.cta_group::1.sync.aligned.b32 %0, %1;" \
                 :: "r"(tmem), "r"((uint32_t)(n)))
#define TC_COMMIT(mbar) \
    asm volatile("tcgen05.commit.cta_group::1.mbarrier::arrive::one.shared::cluster.b64 [%0];" \
                 :: "r"(mbar) : "memory")
#define TC_WAIT_LD()  asm volatile("tcgen05.wait::ld.sync.aligned;" ::: "memory")
#define TC_WAIT_ST()  asm volatile("tcgen05.wait::st.sync.aligned;" ::: "memory")
#define TC_FENCE_AFTER()  asm volatile("tcgen05.fence::after_thread_sync;" ::: "memory")
#define TC_FENCE_BEFORE() asm volatile("tcgen05.fence::before_thread_sync;" ::: "memory")
#define FENCE_PROXY() asm volatile("fence.proxy.async.shared::cta;" ::: "memory")
#define CP_ASYNC16(smem_addr, gptr) \
    asm volatile("cp.async.cg.shared.global [%0], [%1], 16;" \
                 :: "r"(smem_addr), "l"(gptr) : "memory")
#define CP_ASYNC_WAIT_ALL() \
    asm volatile("cp.async.commit_group;\n\tcp.async.wait_group 0;" ::: "memory")
#define MBAR_INIT(mbar, cnt) \
    asm volatile("mbarrier.init.shared.b64 [%0], %1;" :: "r"(mbar), "r"((uint32_t)(cnt)) : "memory")
#define MBAR_INVAL(mbar) \
    asm volatile("mbarrier.inval.shared.b64 [%0];" :: "r"(mbar) : "memory")
#define MBAR_ARRIVE(mbar) \
    asm volatile("mbarrier.arrive.shared.b64 _, [%0];" :: "r"(mbar) : "memory")
#define MBAR_WAIT(mbar, parity) do {                                            \
    uint32_t _m = (mbar); uint32_t _p = (parity); uint32_t _d;                  \
    asm volatile("{\n\t.reg .pred p;\n\t"                                       \
        "mbarrier.try_wait.parity.acquire.cta.shared::cta.b64 p, [%1], %2;\n\t" \
        "selp.b32 %0, 1, 0, p;\n\t}" : "=r"(_d) : "r"(_m), "r"(_p) : "memory"); \
    if (!_d) {                                                                  \
        asm volatile("{\n\t.reg .pred P1;\n\t"                                  \
            "WL_%=:\n\t"                                                        \
            "mbarrier.try_wait.parity.acquire.cta.shared::cta.b64 P1, [%0], %1, 0x989680;\n\t" \
            "@P1 bra.uni WD_%=;\n\t"                                            \
            "bra.uni WL_%=;\n\t"                                                \
            "WD_%=:\n\t}" :: "r"(_m), "r"(_p) : "memory");                      \
    }                                                                           \
} while (0)

// TS-mode MMA: A in TMEM, B via smem descriptor.
__device__ __forceinline__ void mma_f16_ts(uint32_t d, uint32_t a_tmem, uint64_t bd,
                                           uint32_t idesc, bool accum) {
    uint32_t e = accum ? 1u : 0u, z = 0u;
    asm volatile("{\n\t.reg .pred p;\n\tsetp.ne.u32 p, %5, 0;\n\t"
                 "tcgen05.mma.cta_group::1.kind::f16 [%0], [%1], %2, %3, {%4,%4,%4,%4}, p;\n\t}"
                 :: "r"(d), "r"(a_tmem), "l"(bd), "r"(idesc), "r"(z), "r"(e) : "memory");
}
// SS-mode MMA: A and B via smem descriptors.
__device__ __forceinline__ void mma_f16_ss(uint32_t d, uint64_t ad, uint64_t bd,
                                           uint32_t idesc, bool accum) {
    uint32_t e = accum ? 1u : 0u, z = 0u;
    asm volatile("{\n\t.reg .pred p;\n\tsetp.ne.u32 p, %5, 0;\n\t"
                 "tcgen05.mma.cta_group::1.kind::f16 [%0], %1, %2, %3, {%4,%4,%4,%4}, p;\n\t}"
                 :: "r"(d), "l"(ad), "l"(bd), "r"(idesc), "r"(z), "r"(e) : "memory");
}
__device__ __forceinline__ void ldtm_x32(uint32_t* r, uint32_t addr) {
    asm volatile("tcgen05.ld.sync.aligned.32x32b.x32.b32 "
        "{%0,%1,%2,%3,%4,%5,%6,%7,%8,%9,%10,%11,%12,%13,%14,%15,"
        "%16,%17,%18,%19,%20,%21,%22,%23,%24,%25,%26,%27,%28,%29,%30,%31}, [%32];"
        : "=r"(r[0]),"=r"(r[1]),"=r"(r[2]),"=r"(r[3]),"=r"(r[4]),"=r"(r[5]),"=r"(r[6]),"=r"(r[7]),
          "=r"(r[8]),"=r"(r[9]),"=r"(r[10]),"=r"(r[11]),"=r"(r[12]),"=r"(r[13]),"=r"(r[14]),"=r"(r[15]),
          "=r"(r[16]),"=r"(r[17]),"=r"(r[18]),"=r"(r[19]),"=r"(r[20]),"=r"(r[21]),"=r"(r[22]),"=r"(r[23]),
          "=r"(r[24]),"=r"(r[25]),"=r"(r[26]),"=r"(r[27]),"=r"(r[28]),"=r"(r[29]),"=r"(r[30]),"=r"(r[31])
        : "r"(addr));
}
__device__ __forceinline__ void sttm_x32(uint32_t addr, const uint32_t* r) {
    asm volatile("tcgen05.st.sync.aligned.32x32b.x32.b32 [%0], "
        "{%1,%2,%3,%4,%5,%6,%7,%8,%9,%10,%11,%12,%13,%14,%15,%16,"
        "%17,%18,%19,%20,%21,%22,%23,%24,%25,%26,%27,%28,%29,%30,%31,%32};"
        :: "r"(addr),
           "r"(r[0]),"r"(r[1]),"r"(r[2]),"r"(r[3]),"r"(r[4]),"r"(r[5]),"r"(r[6]),"r"(r[7]),
           "r"(r[8]),"r"(r[9]),"r"(r[10]),"r"(r[11]),"r"(r[12]),"r"(r[13]),"r"(r[14]),"r"(r[15]),
           "r"(r[16]),"r"(r[17]),"r"(r[18]),"r"(r[19]),"r"(r[20]),"r"(r[21]),"r"(r[22]),"r"(r[23]),
           "r"(r[24]),"r"(r[25]),"r"(r[26]),"r"(r[27]),"r"(r[28]),"r"(r[29]),"r"(r[30]),"r"(r[31])
        : "memory");
}
__device__ __forceinline__ uint64_t make_desc(uint32_t addr) {
    const uint64_t base = (2ull << 61) | (1ull << 46) | (64ull << 32) | (1ull << 16);
    return base | ((uint64_t)(addr >> 4) & 0x3FFF);
}
#define SWZ(o) ((o) ^ (((o) >> 3) & 0x70))
#endif  // HAS_TCGEN05

// ---------------- fused prep kernel: hsplit + cbsplit + wsq in one launch ----------------
#define HS_TOT (MROWS * DDIM / 4)                 // 2,097,152 float4 items
#define CS_TOT (NLAYERS * NCW * DDIM / 4)         // 393,216 float4 items
#define WQ_TOT (NLAYERS * NCW)                    // 6,144 row items
#define PREP_TOT (HS_TOT + CS_TOT + WQ_TOT)

__global__ void prep_kernel(const float* __restrict__ hin, const float* __restrict__ cb) {
    size_t f = (size_t)blockIdx.x * 256 + threadIdx.x;
    if (f < HS_TOT) {
        float4 v = reinterpret_cast<const float4*>(hin)[f];
        float e[4] = {-2.f * v.x, -2.f * v.y, -2.f * v.z, -2.f * v.w};
        __nv_bfloat16 h[4], m[4];
#pragma unroll
        for (int k = 0; k < 4; k++) split2(e[k], h[k], m[k]);
        reinterpret_cast<uint2*>(g_as[0])[f] = make_uint2(pkbf(h[0], h[1]), pkbf(h[2], h[3]));
        reinterpret_cast<uint2*>(g_as[1])[f] = make_uint2(pkbf(m[0], m[1]), pkbf(m[2], m[3]));
    } else if (f < HS_TOT + CS_TOT) {
        size_t i4 = f - HS_TOT;
        float4 v = reinterpret_cast<const float4*>(cb)[i4];
        float e[4] = {v.x, v.y, v.z, v.w};
        __nv_bfloat16 h[4], m[4];
#pragma unroll
        for (int k = 0; k < 4; k++) split2(e[k], h[k], m[k]);
        reinterpret_cast<uint2*>(g_bs[0])[i4] = make_uint2(pkbf(h[0], h[1]), pkbf(h[2], h[3]));
        reinterpret_cast<uint2*>(g_bs[1])[i4] = make_uint2(pkbf(m[0], m[1]), pkbf(m[2], m[3]));
    } else if (f < PREP_TOT) {
        int r = (int)(f - HS_TOT - CS_TOT);
        const float4* p = reinterpret_cast<const float4*>(cb + (size_t)r * DDIM);
        float s = 0.f;
#pragma unroll
        for (int i = 0; i < DDIM / 4; i++) {
            float4 v = p[i];
            s += v.x * v.x + v.y * v.y + v.z * v.z + v.w * v.w;
        }
        g_wsq[r] = s;
    }
}

// ---------------- main fused layer kernel ----------------
template <int LAYER>
__global__ void __launch_bounds__(TPB, 2)
rvq_tc_kernel(const float* __restrict__ hin,
              const float* __restrict__ codebooks,
              float* __restrict__ qout,
              float* __restrict__ idxout)
{
#if HAS_TCGEN05
    extern __shared__ char dsm_raw[];
    __shared__ float swsq[NCW];
    __shared__ int sIdx[MT];
    __shared__ uint32_t sTmem[1];
    __shared__ __align__(8) unsigned long long sBar[6];
    // sBar: 0,1 = full[stage]; 2,3 = done[stage]; 4 = tile-done; 5 = readers-done

    const int tid = threadIdx.x;
    const int wid = tid >> 5;
    const int row0 = blockIdx.x * MT;

    uint32_t dynb = (smem_u32(dsm_raw) + 1023u) & ~1023u;   // 1024-aligned stage base
    const uint32_t mbFull0 = smem_u32(&sBar[0]);
    const uint32_t mbFull1 = smem_u32(&sBar[1]);
    const uint32_t mbDone0 = smem_u32(&sBar[2]);
    const uint32_t mbDone1 = smem_u32(&sBar[3]);
    const uint32_t mbNT    = smem_u32(&sBar[4]);
    const uint32_t mbRead  = smem_u32(&sBar[5]);
    const uint32_t tptr = smem_u32(&sTmem[0]);

    const float* rin = (LAYER == 0) ? hin : g_res;
    const float* cb  = codebooks + (size_t)LAYER * NCW * DDIM;

    const __nv_bfloat16* ah = g_as[0] + (size_t)row0 * DDIM;   // A h-split (TMEM-bound)
    const __nv_bfloat16* am = g_as[1] + (size_t)row0 * DDIM;   // A m-split (streamed)
    const __nv_bfloat16* bh = g_bs[0] + (size_t)LAYER * NCW * DDIM;
    const __nv_bfloat16* bm = g_bs[1] + (size_t)LAYER * NCW * DDIM;

    if (wid == 0) {
        TC_ALLOC(tptr, 256);   // D: cols 0..127, A-h (full K): cols 128..255
        TC_RELINQ();
    }
    if (tid == 0) {
        MBAR_INIT(mbFull0, 128);
        MBAR_INIT(mbFull1, 128);
        MBAR_INIT(mbDone0, 1);
        MBAR_INIT(mbDone1, 1);
        MBAR_INIT(mbNT, 1);
        MBAR_INIT(mbRead, 128);
    }
    for (int i = tid; i < NCW; i += TPB) swsq[i] = g_wsq[LAYER * NCW + i];
    __syncthreads();
    const uint32_t tmem = sTmem[0];

    if (tid < 128) {
        // ---- consumers (warps 0-3) + MMA issuer (tid 0) ----
        const uint32_t woff = ((uint32_t)tid >> 5) << 21;

        // Load A-h split (row = tid, 256 bf16 = 128 TMEM cols) into TMEM.
        {
            const uint4* src = reinterpret_cast<const uint4*>(ah + (size_t)tid * DDIM);
#pragma unroll
            for (int g = 0; g < 4; g++) {
                uint32_t u[32];
#pragma unroll
                for (int q = 0; q < 8; q++) {
                    uint4 v = src[g * 8 + q];
                    u[q * 4 + 0] = v.x; u[q * 4 + 1] = v.y;
                    u[q * 4 + 2] = v.z; u[q * 4 + 3] = v.w;
                }
                sttm_x32(tmem + 128 + g * 32 + woff, u);
            }
        }
        TC_WAIT_ST();
        TC_FENCE_BEFORE();
        asm volatile("bar.sync 1, 128;" ::: "memory");   // all A-h rows in TMEM

        float bestS = 3.4e38f, secS = 3.4e38f;
        int   bestI = 0,       secI = 0;

#pragma unroll 1
        for (int nt = 0; nt < NTILES; nt++) {
            if (tid == 0) {
                if (nt > 0) MBAR_WAIT(mbRead, (nt - 1) & 1);  // D readers done
#pragma unroll 1
                for (int kc = 0; kc < NCHUNK; kc++) {
                    int itc = nt * NCHUNK + kc;
                    int st  = itc & 1;
                    int u   = itc >> 1;
                    MBAR_WAIT(st ? mbFull1 : mbFull0, u & 1);
                    uint64_t am_d = make_desc(dynb + st * STAGE_BYTES + 0 * SPLIT_BYTES);
                    uint64_t bh_d = make_desc(dynb + st * STAGE_BYTES + 1 * SPLIT_BYTES);
                    uint64_t bm_d = make_desc(dynb + st * STAGE_BYTES + 2 * SPLIT_BYTES);
                    uint32_t ah_t = tmem + 128 + kc * 32;
#pragma unroll
                    for (int ks = 0; ks < 4; ks++) {
                        bool first = (kc == 0 && ks == 0);
                        mma_f16_ts(tmem, ah_t + ks * 8, bh_d + ks * 2, MMA_IDESC, !first);  // hh
                        mma_f16_ts(tmem, ah_t + ks * 8, bm_d + ks * 2, MMA_IDESC, true);    // hm
                        mma_f16_ss(tmem, am_d + ks * 2, bh_d + ks * 2, MMA_IDESC, true);    // mh
                    }
                    TC_COMMIT(st ? mbDone1 : mbDone0);
                    if (kc == NCHUNK - 1) TC_COMMIT(mbNT);
                }
            }
            MBAR_WAIT(mbNT, nt & 1);   // all of this tile's MMAs complete
            TC_FENCE_AFTER();
#pragma unroll
            for (int g = 0; g < 3; g++) {
                uint32_t d[32];
                ldtm_x32(d, tmem + g * 32);
                TC_WAIT_LD();
#pragma unroll
                for (int j = 0; j < 32; j++) {
                    int col = nt * NT + g * 32 + j;
                    float s = swsq[col] + __uint_as_float(d[j]);  // wsq - 2 r.w
                    if (s < bestS) {
                        secS = bestS; secI = bestI;
                        bestS = s;    bestI = col;
                    } else if (s < secS) {
                        secS = s; secI = col;
                    }
                }
            }
            // Last group: release D before scanning (scan runs off the blocking path).
            {
                uint32_t d[32];
                ldtm_x32(d, tmem + 96);
                TC_WAIT_LD();
                TC_FENCE_BEFORE();
                MBAR_ARRIVE(mbRead);   // D fully read: next tile's MMAs may start
#pragma unroll
                for (int j = 0; j < 32; j++) {
                    int col = nt * NT + 96 + j;
                    float s = swsq[col] + __uint_as_float(d[j]);
                    if (s < bestS) {
                        secS = bestS; secI = bestI;
                        bestS = s;    bestI = col;
                    } else if (s < secS) {
                        secS = s; secI = col;
                    }
                }
            }
        }

        // Exact fp32 rescore when contested (round-3-proven decision procedure).
        int win = bestI;
        if (secS - bestS < RESCORE_DELTA) {
            int c1 = bestI, c2 = secI;
            const float4* rp  = reinterpret_cast<const float4*>(rin + (size_t)(row0 + tid) * DDIM);
            const float4* w1p = reinterpret_cast<const float4*>(cb + (size_t)c1 * DDIM);
            const float4* w2p = reinterpret_cast<const float4*>(cb + (size_t)c2 * DDIM);
            float a1 = 0.f, a2 = 0.f;
#pragma unroll 8
            for (int i = 0; i < DDIM / 4; i++) {
                float4 rv = rp[i];
                float4 w1 = w1p[i];
                float4 w2 = w2p[i];
                a1 = fmaf(rv.x, w1.x, a1); a1 = fmaf(rv.y, w1.y, a1);
                a1 = fmaf(rv.z, w1.z, a1); a1 = fmaf(rv.w, w1.w, a1);
                a2 = fmaf(rv.x, w2.x, a2); a2 = fmaf(rv.y, w2.y, a2);
                a2 = fmaf(rv.z, w2.z, a2); a2 = fmaf(rv.w, w2.w, a2);
            }
            float s1 = fmaf(-2.f, a1, swsq[c1]);
            float s2 = fmaf(-2.f, a2, swsq[c2]);
            win = (s2 < s1 || (s2 == s1 && c2 < c1)) ? c2 : c1;
        }
        sIdx[tid] = win;
        if (idxout) idxout[LAYER * MROWS + row0 + tid] = (float)win;
    } else {
        // ---- producers (warps 4-7): A-m + B-h + B-m chunks via cp.async, 2-stage ----
        const int ptid = tid - 128;
#pragma unroll 1
        for (int itc = 0; itc < NTILES * NCHUNK; itc++) {
            int st = itc & 1;
            int u  = itc >> 1;
            if (u > 0) MBAR_WAIT(st ? mbDone1 : mbDone0, (u - 1) & 1);
            int nt = itc >> 2;
            int kc = itc & 3;
#pragma unroll
            for (int i = 0; i < 24; i++) {
                int f   = i * 128 + ptid;     // 0..3071
                int s   = f >> 10;            // sub-tile: 0=A-m, 1=B-h, 2=B-m
                int rem = f & 1023;
                int r   = rem >> 3;           // row 0..127
                int j   = rem & 7;            // 16B group within 128B row
                const __nv_bfloat16* src;
                if (s == 0)      src = am + (size_t)r * DDIM + kc * KC + j * 8;
                else if (s == 1) src = bh + (size_t)(nt * NT + r) * DDIM + kc * KC + j * 8;
                else             src = bm + (size_t)(nt * NT + r) * DDIM + kc * KC + j * 8;
                uint32_t dst = dynb + st * STAGE_BYTES + s * SPLIT_BYTES + SWZ(r * 128 + j * 16);
                CP_ASYNC16(dst, src);
            }
            CP_ASYNC_WAIT_ALL();
            FENCE_PROXY();
            MBAR_ARRIVE(st ? mbFull1 : mbFull0);
        }
    }
    __syncthreads();

    // fused epilogue: gather winner, quant accumulate, residual + next-layer splits
#pragma unroll 4
    for (int it = 0; it < 32; it++) {
        int f   = it * TPB + tid;   // 0..8191
        int rr  = f >> 6;           // row 0..127
        int c4  = f & 63;           // float4 over D
        int row = row0 + rr;
        int w   = sIdx[rr];
        float4 wv = *reinterpret_cast<const float4*>(cb + (size_t)w * DDIM + c4 * 4);
        float4* qp = reinterpret_cast<float4*>(qout + (size_t)row * DDIM + c4 * 4);
        if (LAYER == 0) {
            *qp = wv;
        } else {
            float4 q = *qp;
            q.x += wv.x; q.y += wv.y; q.z += wv.z; q.w += wv.w;
            *qp = q;
        }
        if (LAYER < 2) {
            float4 rv = *reinterpret_cast<const float4*>(rin + (size_t)row * DDIM + c4 * 4);
            float4 nr = make_float4(rv.x - wv.x, rv.y - wv.y, rv.z - wv.z, rv.w - wv.w);
            *reinterpret_cast<float4*>(g_res + (size_t)row * DDIM + c4 * 4) = nr;
            float e[4] = {-2.f * nr.x, -2.f * nr.y, -2.f * nr.z, -2.f * nr.w};
            __nv_bfloat16 h[4], m[4];
#pragma unroll
            for (int k = 0; k < 4; k++) split2(e[k], h[k], m[k]);
            size_t o2 = ((size_t)row * DDIM + c4 * 4) / 4;   // uint2 index
            reinterpret_cast<uint2*>(g_as[0])[o2] = make_uint2(pkbf(h[0], h[1]), pkbf(h[2], h[3]));
            reinterpret_cast<uint2*>(g_as[1])[o2] = make_uint2(pkbf(m[0], m[1]), pkbf(m[2], m[3]));
        }
    }

    __syncthreads();
    if (tid == 0) {
        MBAR_INVAL(mbFull0); MBAR_INVAL(mbFull1);
        MBAR_INVAL(mbDone0); MBAR_INVAL(mbDone1);
        MBAR_INVAL(mbNT);    MBAR_INVAL(mbRead);
    }
    __syncthreads();
    if (wid == 0) TC_DEALLOC(tmem, 256);

#else  // ---------------- fallback: exact-fp32 FFMA path (round-3 body) ----------------

    __shared__ unsigned int smemU[4480];
    float* As = reinterpret_cast<float*>(smemU);                 // [FB_BK][FB_LDSROW]
    float* Bs = As + FB_BK * FB_LDSROW;                          // [FB_BK][FB_LDSROW]
    float* redS = reinterpret_cast<float*>(smemU);               // [128][17]
    int*   redI = reinterpret_cast<int*>(smemU + 128 * 17);      // [128][17]
    __shared__ int sIdx[MT];

    const float* rin = (LAYER == 0) ? hin : g_res;
    const float* cb  = codebooks + (size_t)LAYER * NCW * DDIM;
    const float* wsq = g_wsq + LAYER * NCW;

    const int tid   = threadIdx.x;
    const int wid   = tid >> 5;
    const int lane  = tid & 31;
    const int warpR = wid >> 1;
    const int warpC = wid & 1;
    const int r     = lane >> 3;
    const int c     = lane & 7;

    const int rowA0 = warpR * 32 + r * 4;
    const int rowA1 = rowA0 + 16;
    const int colB0 = warpC * 64 + c * 4;
    const int colB1 = colB0 + 32;

    const int row0 = blockIdx.x * MT;
    const int ldrow = tid >> 2;
    const int ldkq  = tid & 3;

    float bestS[8];
    int   bestI[8];
#pragma unroll
    for (int j = 0; j < 8; j++) { bestS[j] = 1e30f; bestI[j] = 0; }

    const float* aG = rin + (size_t)row0 * DDIM;

#pragma unroll 1
    for (int nt = 0; nt < NCW / NT; nt++) {
        float acc[8][8];
#pragma unroll
        for (int j = 0; j < 8; j++)
#pragma unroll
            for (int p = 0; p < 8; p++) acc[j][p] = 0.f;

        const float* bG = cb + (size_t)(nt * NT) * DDIM;

#pragma unroll 1
        for (int kc = 0; kc < DDIM / FB_BK; kc++) {
            __syncthreads();
#pragma unroll
            for (int i = 0; i < 2; i++) {
                int row = i * 64 + ldrow;
                float4 av = *reinterpret_cast<const float4*>(
                    aG + (size_t)row * DDIM + kc * FB_BK + ldkq * 4);
                float4 bv = *reinterpret_cast<const float4*>(
                    bG + (size_t)row * DDIM + kc * FB_BK + ldkq * 4);
                As[(ldkq * 4 + 0) * FB_LDSROW + row] = av.x;
                As[(ldkq * 4 + 1) * FB_LDSROW + row] = av.y;
                As[(ldkq * 4 + 2) * FB_LDSROW + row] = av.z;
                As[(ldkq * 4 + 3) * FB_LDSROW + row] = av.w;
                Bs[(ldkq * 4 + 0) * FB_LDSROW + row] = bv.x;
                Bs[(ldkq * 4 + 1) * FB_LDSROW + row] = bv.y;
                Bs[(ldkq * 4 + 2) * FB_LDSROW + row] = bv.z;
                Bs[(ldkq * 4 + 3) * FB_LDSROW + row] = bv.w;
            }
            __syncthreads();

#pragma unroll
            for (int k = 0; k < FB_BK; k++) {
                const float* ak = As + k * FB_LDSROW;
                const float* bk = Bs + k * FB_LDSROW;
                float4 a0 = *reinterpret_cast<const float4*>(ak + rowA0);
                float4 a1 = *reinterpret_cast<const float4*>(ak + rowA1);
                float4 b0 = *reinterpret_cast<const float4*>(bk + colB0);
                float4 b1 = *reinterpret_cast<const float4*>(bk + colB1);
                float af[8] = {a0.x, a0.y, a0.z, a0.w, a1.x, a1.y, a1.z, a1.w};
                float bf[8] = {b0.x, b0.y, b0.z, b0.w, b1.x, b1.y, b1.z, b1.w};
#pragma unroll
                for (int j = 0; j < 8; j++)
#pragma unroll
                    for (int p = 0; p < 8; p++)
                        acc[j][p] = fmaf(af[j], bf[p], acc[j][p]);
            }
        }

        float4 w0 = *reinterpret_cast<const float4*>(wsq + nt * NT + colB0);
        float4 w1 = *reinterpret_cast<const float4*>(wsq + nt * NT + colB1);
        float wv[8] = {w0.x, w0.y, w0.z, w0.w, w1.x, w1.y, w1.z, w1.w};
#pragma unroll
        for (int j = 0; j < 8; j++) {
#pragma unroll
            for (int p = 0; p < 8; p++) {
                int col = nt * NT + ((p < 4) ? (colB0 + p) : (colB1 + p - 4));
                float s = fmaf(-2.f, acc[j][p], wv[p]);
                if (s < bestS[j]) { bestS[j] = s; bestI[j] = col; }
            }
        }
    }

    __syncthreads();
    {
        int slot = warpC * 8 + c;
#pragma unroll
        for (int j = 0; j < 8; j++) {
            int rl = warpR * 32 + ((j < 4) ? 0 : 16) + r * 4 + (j & 3);
            redS[rl * 17 + slot] = bestS[j];
            redI[rl * 17 + slot] = bestI[j];
        }
    }
    __syncthreads();
    if (tid < MT) {
        float bs = redS[tid * 17];
        int   bi = redI[tid * 17];
#pragma unroll
        for (int x = 1; x < 16; x++) {
            float s  = redS[tid * 17 + x];
            int   ii = redI[tid * 17 + x];
            if (s < bs || (s == bs && ii < bi)) { bs = s; bi = ii; }
        }
        sIdx[tid] = bi;
        if (idxout) idxout[LAYER * MROWS + row0 + tid] = (float)bi;
    }
    __syncthreads();

#pragma unroll 4
    for (int it = 0; it < 32; it++) {
        int f   = it * TPB + tid;
        int rr  = f >> 6;
        int c4  = f & 63;
        int row = row0 + rr;
        int w   = sIdx[rr];
        float4 wv = *reinterpret_cast<const float4*>(cb + (size_t)w * DDIM + c4 * 4);
        float4 rv = *reinterpret_cast<const float4*>(rin + (size_t)row * DDIM + c4 * 4);
        float4 nr = make_float4(rv.x - wv.x, rv.y - wv.y, rv.z - wv.z, rv.w - wv.w);
        *reinterpret_cast<float4*>(g_res + (size_t)row * DDIM + c4 * 4) = nr;
        float4* qp = reinterpret_cast<float4*>(qout + (size_t)row * DDIM + c4 * 4);
        if (LAYER == 0) {
            *qp = wv;
        } else {
            float4 q = *qp;
            q.x += wv.x; q.y += wv.y; q.z += wv.z; q.w += wv.w;
            *qp = q;
        }
    }
#endif  // HAS_TCGEN05
}

// ---------------- host launcher ----------------
extern "C" void kernel_launch(void* const* d_in, const int* in_sizes, int n_in,
                              void* d_out, int out_size) {
    (void)in_sizes; (void)n_in;
    const float* h  = (const float*)d_in[0];
    const float* cb = (const float*)d_in[1];
    float* out = (float*)d_out;

    const long long QN = (long long)MROWS * DDIM;     // 8,388,608
    const long long IN = (long long)NLAYERS * MROWS;  // 98,304
    float* qout   = out;
    float* idxout = ((long long)out_size >= QN + IN) ? out + QN : nullptr;

    cudaFuncSetAttribute(rvq_tc_kernel<0>, cudaFuncAttributeMaxDynamicSharedMemorySize, DSM_BYTES);
    cudaFuncSetAttribute(rvq_tc_kernel<1>, cudaFuncAttributeMaxDynamicSharedMemorySize, DSM_BYTES);
    cudaFuncSetAttribute(rvq_tc_kernel<2>, cudaFuncAttributeMaxDynamicSharedMemorySize, DSM_BYTES);

    prep_kernel<<<(PREP_TOT + 255) / 256, 256>>>(h, cb);

    rvq_tc_kernel<0><<<MROWS / MT, TPB, DSM_BYTES>>>(h, cb, qout, idxout);
    rvq_tc_kernel<1><<<MROWS / MT, TPB, DSM_BYTES>>>(h, cb, qout, idxout);
    rvq_tc_kernel<2><<<MROWS / MT, TPB, DSM_BYTES>>>(h, cb, qout, idxout);
}